// round 5
// baseline (speedup 1.0000x reference)
#include <cuda_runtime.h>

// MeshConvPoint: B=4, C_IN=64, V=50000, C_OUT=128, K=7
//
// Pipeline (all on default stream, graph-capturable, no allocations):
//   1) transpose_kernel : x [B,C,V]   -> g_xT [B,V,C]   (coalesced gathers later)
//   2) wtprep_kernel    : W [O,C,K]   -> g_Wt [C*K, O]  (coalesced smem loads later)
//   3) mesh_main        : fused gather + symm features + fp32x2 GEMM + bias
//
// mesh_main: 1 block = 64 points x 128 outputs, 256 threads.
//   - channel chunks of 16 (112 K-values per chunk, 4 chunks = 448)
//   - G staged transposed in smem [kk][p] so point pairs read as 8B broadcasts
//   - inner loop uses fma.rn.f32x2 (FFMA2): 2 fp32 FMA per instruction
//   - epilogue restages through smem for coalesced global stores
//
// R2 fix: Gi is int32 on disk (JAX x64 disabled downgrades jnp.int64).
//         Read as int32 with an in-kernel dtype probe for safety.

#define BATCH   4
#define CIN     64
#define NV      50000
#define COUT    128
#define NK      7
#define CK      (CIN * NK)        // 448
#define TP      64                // points per tile
#define NTHREADS 256
#define CHUNK_C  16
#define CHUNK_KK (CHUNK_C * NK)   // 112
#define NCHUNK   (CIN / CHUNK_C)  // 4
#define WC_PITCH 132              // padded row (floats) for Wc and sOut
#define NPTS    (BATCH * NV)      // 200000
#define NTILES  (NPTS / TP)       // 3125 (exact)

// ---- scratch (static device globals; no runtime allocation) ----
__device__ float g_xT[(size_t)BATCH * NV * CIN];   // 51.2 MB
__device__ float g_Wt[CK * COUT];                  // 229 KB

// ---- packed fp32x2 helpers ----
__device__ __forceinline__ unsigned long long pk2(float lo, float hi) {
    unsigned long long r;
    asm("mov.b64 %0, {%1, %2};" : "=l"(r) : "f"(lo), "f"(hi));
    return r;
}
__device__ __forceinline__ float2 upk2(unsigned long long a) {
    float2 r;
    asm("mov.b64 {%0, %1}, %2;" : "=f"(r.x), "=f"(r.y) : "l"(a));
    return r;
}
__device__ __forceinline__ void fma2(unsigned long long& d,
                                     unsigned long long a,
                                     unsigned long long b) {
    asm("fma.rn.f32x2 %0, %1, %2, %3;" : "=l"(d) : "l"(a), "l"(b), "l"(d));
}

// ---- 1) transpose x [B,C,V] -> xT [B,V,C] ----
__global__ void transpose_kernel(const float* __restrict__ x) {
    __shared__ float tile[32][33];
    int b  = blockIdx.z;
    int cb = blockIdx.y * 32;
    int vb = blockIdx.x * 32;
    int tx = threadIdx.x, ty = threadIdx.y;   // 32 x 8

#pragma unroll
    for (int i = 0; i < 32; i += 8) {
        int c = cb + ty + i;
        int v = vb + tx;
        if (v < NV)
            tile[ty + i][tx] = x[((size_t)(b * CIN + c)) * NV + v];
    }
    __syncthreads();
#pragma unroll
    for (int i = 0; i < 32; i += 8) {
        int v = vb + ty + i;
        int c = cb + tx;
        if (v < NV)
            g_xT[((size_t)(b * NV + v)) * CIN + c] = tile[tx][ty + i];
    }
}

// ---- 2) W [O][C][K] -> Wt [C*K][O] ----
__global__ void wtprep_kernel(const float* __restrict__ W) {
    int i = blockIdx.x * 256 + threadIdx.x;
    if (i < CK * COUT) {
        int kk = i >> 7;          // 0..447
        int o  = i & 127;
        g_Wt[i] = W[o * CK + kk];
    }
}

// ---- shared memory layout (bytes) ----
#define OFF_WC   0                                  // Wc  [112][132] f32 = 59136
#define OFF_FS   59136                              // fs  [4][16][64] f32 = 16384 (sOut overlaps here)
#define OFF_GST  (59136 + 16384)                    // GsT [112][64] f32 = 28672
#define OFF_IDX  (59136 + 16384 + 28672)            // idx [64][4] int  = 1024
#define OFF_PB   (OFF_IDX + 1024)                   // pbase [64] int   = 256
#define SMEM_TOTAL (OFF_PB + 256)                   // 105472 bytes

// ---- 3) fused main kernel ----
__global__ void __launch_bounds__(NTHREADS, 2)
mesh_main(const int* __restrict__ Gi32,
          const float* __restrict__ bias,
          float* __restrict__ out) {
    extern __shared__ char sm[];
    float* Wc    = (float*)(sm + OFF_WC);    // [112][WC_PITCH]
    float* fs    = (float*)(sm + OFF_FS);    // [(j*16+c)*64 + p]
    float* GsT   = (float*)(sm + OFF_GST);   // [kk*64 + p]
    int*   idxs  = (int*)  (sm + OFF_IDX);   // [p*4 + j]
    int*   pbase = (int*)  (sm + OFF_PB);    // [p] = b*NV
    float* sOut  = (float*)(sm + OFF_FS);    // [vl*WC_PITCH + o] (reuses fs+GsT)

    const int t  = threadIdx.x;
    const int p0 = blockIdx.x * TP;

    // ---- dtype probe + load Gi indices for this tile (one (p,j) per thread) ----
    {
        // If the buffer is really int64, the high words of small indices are 0.
        // If int32, these are random neighbor indices (all-zero prob ~1e-19).
        bool is64 = ((Gi32[1] | Gi32[3] | Gi32[5] | Gi32[7]) == 0);
        int p  = t >> 2, j = t & 3;
        int pg = p0 + p;
        int b  = pg / NV;
        int e  = pg * 4 + j;
        int idx = is64 ? Gi32[2 * e] : Gi32[e];   // low word if int64
        idxs[t] = (idx >= 0 && idx < NV) ? idx : -1;   // -1 => padded zero row
        if (j == 0) pbase[p] = b * NV;
    }

    const int po  = t & 31;           // output group (4 outputs)
    const int pp  = t >> 5;           // point group (8 points)
    const int po4 = po * 4;
    const int pp8 = pp * 8;

    const float b0 = bias[po4 + 0];
    const float b1 = bias[po4 + 1];
    const float b2 = bias[po4 + 2];
    const float b3 = bias[po4 + 3];

    unsigned long long acc[16];       // [u][j]: points (pp8+2u, pp8+2u+1) x output (po4+j)
#pragma unroll
    for (int i = 0; i < 16; i++) acc[i] = 0ULL;

    for (int chunk = 0; chunk < NCHUNK; chunk++) {
        const int c0 = chunk * CHUNK_C;
        __syncthreads();   // previous-chunk GEMM done reading Wc/GsT; idx/pbase visible

        // load W chunk: Wt rows [c0*7, c0*7+112) -> Wc[kk][o], coalesced
        for (int l = t; l < CHUNK_KK * COUT; l += NTHREADS) {
            int kk = l >> 7;
            int o  = l & 127;
            Wc[kk * WC_PITCH + o] = g_Wt[(c0 * NK + kk) * COUT + o];
        }

        // gather f: thread (p,j) loads 16 contiguous channels (4x float4)
        {
            int p = t >> 2, j = t & 3;
            int idx = idxs[t];
            if (idx >= 0) {
                const float4* src = (const float4*)&g_xT[((size_t)(pbase[p] + idx)) * CIN + c0];
#pragma unroll
                for (int q = 0; q < 4; q++) {
                    float4 v4 = src[q];
                    fs[(j * 16 + q * 4 + 0) * 64 + p] = v4.x;
                    fs[(j * 16 + q * 4 + 1) * 64 + p] = v4.y;
                    fs[(j * 16 + q * 4 + 2) * 64 + p] = v4.z;
                    fs[(j * 16 + q * 4 + 3) * 64 + p] = v4.w;
                }
            } else {
#pragma unroll
                for (int q = 0; q < 16; q++)
                    fs[(j * 16 + q) * 64 + p] = 0.0f;
            }
        }
        __syncthreads();

        // symmetric features -> GsT[kk][p]
        for (int l = t; l < TP * CHUNK_C; l += NTHREADS) {
            int p = l & 63;
            int c = l >> 6;
            float f0 = fs[(c)      * 64 + p];
            float f1 = fs[(16 + c) * 64 + p];
            float f2 = fs[(32 + c) * 64 + p];
            float f3 = fs[(48 + c) * 64 + p];
            float p12 = f1 * f2, p13 = f1 * f3, p23 = f2 * f3;
            float g1 = f1 + f2 + f3;
            float g2 = p12 * f3;
            float g3 = p12 + p13 + p23;
            float g4 = f1 * f1 + f2 * f2 + f3 * f3;
            float g5 = fabsf(f1 - f2) + fabsf(f1 - f3) + fabsf(f2 - f3);
            float g6 = f1 * f1 * f1 + f2 * f2 * f2 + f3 * f3 * f3;
            int kb = c * NK;
            GsT[(kb + 0) * 64 + p] = f0;
            GsT[(kb + 1) * 64 + p] = g1;
            GsT[(kb + 2) * 64 + p] = g2;
            GsT[(kb + 3) * 64 + p] = g3;
            GsT[(kb + 4) * 64 + p] = g4;
            GsT[(kb + 5) * 64 + p] = g5;
            GsT[(kb + 6) * 64 + p] = g6;
        }
        __syncthreads();

        // GEMM: acc[p][o] += sum_kk GsT[kk][p] * Wc[kk][o]   (packed f32x2)
#pragma unroll 2
        for (int kk = 0; kk < CHUNK_KK; kk++) {
            const float4 w = *(const float4*)&Wc[kk * WC_PITCH + po4];
            unsigned long long w0 = pk2(w.x, w.x);
            unsigned long long w1 = pk2(w.y, w.y);
            unsigned long long w2 = pk2(w.z, w.z);
            unsigned long long w3 = pk2(w.w, w.w);
            const unsigned long long* gp =
                (const unsigned long long*)&GsT[kk * 64 + pp8];
            unsigned long long gq0 = gp[0];
            unsigned long long gq1 = gp[1];
            unsigned long long gq2 = gp[2];
            unsigned long long gq3 = gp[3];
            fma2(acc[0],  gq0, w0); fma2(acc[1],  gq0, w1);
            fma2(acc[2],  gq0, w2); fma2(acc[3],  gq0, w3);
            fma2(acc[4],  gq1, w0); fma2(acc[5],  gq1, w1);
            fma2(acc[6],  gq1, w2); fma2(acc[7],  gq1, w3);
            fma2(acc[8],  gq2, w0); fma2(acc[9],  gq2, w1);
            fma2(acc[10], gq2, w2); fma2(acc[11], gq2, w3);
            fma2(acc[12], gq3, w0); fma2(acc[13], gq3, w1);
            fma2(acc[14], gq3, w2); fma2(acc[15], gq3, w3);
        }
    }
    __syncthreads();   // done with fs/GsT; safe to overwrite with sOut

    // epilogue: acc -> sOut[vl][o] (+bias), vectorized, conflict-free rows
#pragma unroll
    for (int u = 0; u < 4; u++) {
        float2 a0 = upk2(acc[u * 4 + 0]);
        float2 a1 = upk2(acc[u * 4 + 1]);
        float2 a2 = upk2(acc[u * 4 + 2]);
        float2 a3 = upk2(acc[u * 4 + 3]);
        float4 lo = make_float4(a0.x + b0, a1.x + b1, a2.x + b2, a3.x + b3);
        float4 hi = make_float4(a0.y + b0, a1.y + b1, a2.y + b2, a3.y + b3);
        *(float4*)&sOut[(pp8 + 2 * u + 0) * WC_PITCH + po4] = lo;
        *(float4*)&sOut[(pp8 + 2 * u + 1) * WC_PITCH + po4] = hi;
    }
    __syncthreads();

    // coalesced global stores: out[b][o][v]
    for (int l = t; l < COUT * TP; l += NTHREADS) {
        int o  = l >> 6;
        int vl = l & 63;
        int pg = p0 + vl;
        int b  = pg / NV;
        int v  = pg - b * NV;
        out[((size_t)(b * COUT + o)) * NV + v] = sOut[vl * WC_PITCH + o];
    }
}

extern "C" void kernel_launch(void* const* d_in, const int* in_sizes, int n_in,
                              void* d_out, int out_size) {
    const float* x    = (const float*)d_in[0];      // [B, C_IN, V, 1]
    const int*   Gi   = (const int*)d_in[1];        // [B, V, 4] (int32 or int64; probed in-kernel)
    const float* W    = (const float*)d_in[2];      // [C_OUT, C_IN, 7]
    const float* bias = (const float*)d_in[3];      // [C_OUT]
    float*       out  = (float*)d_out;              // [B, C_OUT, V, 1]

    static bool attr_set = false;
    if (!attr_set) {
        cudaFuncSetAttribute(mesh_main,
                             cudaFuncAttributeMaxDynamicSharedMemorySize,
                             SMEM_TOTAL);
        attr_set = true;
    }

    transpose_kernel<<<dim3((NV + 31) / 32, CIN / 32, BATCH), dim3(32, 8)>>>(x);
    wtprep_kernel<<<(CK * COUT + 255) / 256, 256>>>(W);
    mesh_main<<<NTILES, NTHREADS, SMEM_TOTAL>>>(Gi, bias, out);
}

// round 8
// speedup vs baseline: 2.1327x; 2.1327x over previous
#include <cuda_runtime.h>
#include <cuda_bf16.h>
#include <cstdint>

// MeshConvPoint via legacy warp-level mma.sync (HMMA), sm_103-safe (no tcgen05).
//   out[pts,128] = G[pts,448] @ W[448,128] + bias, fused with gather.
//   bf16 3-term split precision: D ~= Ah*Bh + Al*Bh + Ah*Bl (fp32 accum).
//
// CTA: 128 points x 128 outputs, 512 threads = 16 warps.
//   warp w: m-tile = (w&7)*16 points, n-half = (w>>3)*64 outputs (8 n8-tiles).
// K = 448 = 4 chunks x 112; per chunk 7 k16-steps. Within a chunk,
// k_local = r*16 + c  (r = kernel-tap 0..6, c = channel 0..15).

#define BATCH    4
#define CIN      64
#define NV       50000
#define COUT     128
#define NK       7
#define CK       (CIN * NK)              // 448
#define NPTS     (BATCH * NV)            // 200000
#define TP       128
#define NTILES   ((NPTS + TP - 1) / TP)  // 1563
#define NTHREADS 512
#define NCHUNK   4                       // 16 channels per chunk
#define KCHUNK   112                     // k per chunk
#define ROWB     240                     // padded row bytes (120 bf16)
#define TILE_B   (128 * ROWB)            // 30720 B per operand tile

// smem layout (bytes)
#define OFF_AHI  0
#define OFF_ALO  (TILE_B)
#define OFF_BHI  (2 * TILE_B)
#define OFF_BLO  (3 * TILE_B)
#define OFF_IDX  (4 * TILE_B)            // 512 ints
#define OFF_BIAS (OFF_IDX + 2048)        // 128 floats
#define SMEM_TOTAL (OFF_BIAS + 512)      // 125440
#define SOUT_PITCH 132                   // epilogue overlay [128][132] f32

// static scratch
__device__ __align__(16) float         g_xT[(size_t)BATCH * NV * CIN];        // 51.2 MB
__device__ __align__(16) __nv_bfloat16 g_Wbf[2][NCHUNK][128][120];            // pre-split W tiles

__device__ __forceinline__ uint32_t smem_u32(const void* p) {
    uint32_t a;
    asm("{ .reg .u64 t; cvta.to.shared.u64 t, %1; cvt.u32.u64 %0, t; }" : "=r"(a) : "l"(p));
    return a;
}
__device__ __forceinline__ void bsplit(float v, uint32_t& h, uint32_t& l) {
    __nv_bfloat16 hb = __float2bfloat16(v);
    h = (uint32_t)__bfloat16_as_ushort(hb);
    float hf = __uint_as_float(h << 16);            // exact bf16 -> f32
    l = (uint32_t)__bfloat16_as_ushort(__float2bfloat16(v - hf));
}

#define LDMX4(r0, r1, r2, r3, addr) \
    asm volatile("ldmatrix.sync.aligned.m8n8.x4.shared.b16 {%0,%1,%2,%3}, [%4];" \
                 : "=r"(r0), "=r"(r1), "=r"(r2), "=r"(r3) : "r"(addr))

#define MMA16816(d, a0, a1, a2, a3, b0, b1) \
    asm volatile("mma.sync.aligned.m16n8k16.row.col.f32.bf16.bf16.f32 " \
                 "{%0,%1,%2,%3}, {%4,%5,%6,%7}, {%8,%9}, {%0,%1,%2,%3};" \
                 : "+f"((d)[0]), "+f"((d)[1]), "+f"((d)[2]), "+f"((d)[3]) \
                 : "r"(a0), "r"(a1), "r"(a2), "r"(a3), "r"(b0), "r"(b1))

// ---- 1) transpose x [B,C,V] -> xT [B,V,C] ----
__global__ void transpose_kernel(const float* __restrict__ x) {
    __shared__ float tile[32][33];
    int b  = blockIdx.z;
    int cb = blockIdx.y * 32;
    int vb = blockIdx.x * 32;
    int tx = threadIdx.x, ty = threadIdx.y;
#pragma unroll
    for (int i = 0; i < 32; i += 8) {
        int c = cb + ty + i, v = vb + tx;
        if (v < NV) tile[ty + i][tx] = x[((size_t)(b * CIN + c)) * NV + v];
    }
    __syncthreads();
#pragma unroll
    for (int i = 0; i < 32; i += 8) {
        int v = vb + ty + i, c = cb + tx;
        if (v < NV) g_xT[((size_t)(b * NV + v)) * CIN + c] = tile[tx][ty + i];
    }
}

// ---- 2) W -> bf16 hi/lo tiles [term][chunk][n=128][k=120], k = r*16 + c ----
__global__ void wprep_kernel(const float* __restrict__ W) {
    int i = blockIdx.x * 256 + threadIdx.x;         // over 4*128*120 = 61440
    if (i >= NCHUNK * 128 * 120) return;
    int kl = i % 120;
    int n  = (i / 120) & 127;
    int ch = i / (120 * 128);
    uint32_t h = 0, l = 0;
    if (kl < KCHUNK) {
        int r = kl >> 4, c = kl & 15;
        float v = W[n * CK + (ch * 16 + c) * NK + r];
        bsplit(v, h, l);
    }
    g_Wbf[0][ch][n][kl] = __ushort_as_bfloat16((unsigned short)h);
    g_Wbf[1][ch][n][kl] = __ushort_as_bfloat16((unsigned short)l);
}

// ---- 3) fused main kernel ----
__global__ void __launch_bounds__(NTHREADS, 1)
mesh_main(const int* __restrict__ Gi32,
          const float* __restrict__ bias,
          float* __restrict__ out) {
    extern __shared__ char sm[];
    const uint32_t sb = smem_u32(sm);
    const int t    = threadIdx.x;
    const int wid  = t >> 5;
    const int lane = t & 31;
    const int p0   = blockIdx.x * TP;

    int*   idxs  = (int*)(sm + OFF_IDX);
    float* sBias = (float*)(sm + OFF_BIAS);

    if (t < COUT) sBias[t] = bias[t];
    {   // resolve gather rows; probe int64-vs-int32 (JAX x64-off downgrade)
        bool is64 = ((Gi32[1] | Gi32[3] | Gi32[5] | Gi32[7]) == 0);
        int p = t >> 2, j = t & 3;
        int pg = p0 + p;
        int row = -1;
        if (pg < NPTS) {
            int raw = is64 ? Gi32[2 * (pg * 4 + j)] : Gi32[pg * 4 + j];
            if (raw >= 0 && raw < NV) row = (pg / NV) * NV + raw;
        }
        idxs[t] = row;
    }

    // warp tiling
    const int mb = (wid & 7) * 16;       // point base of warp's m16
    const int nh = (wid >> 3) * 64;      // output base of warp's n-half

    // ldmatrix lane-address components
    const int mi    = lane >> 3;
    const int rowin = lane & 7;
    // A: t0=(m0,k0) t1=(m8,k0) t2=(m0,k8) t3=(m8,k8)
    const uint32_t aOff = (uint32_t)(mb + (mi & 1) * 8 + rowin) * ROWB + (uint32_t)(mi >> 1) * 16;
    // B: t0=(nt,k0) t1=(nt,k8) t2=(nt+1,k0) t3=(nt+1,k8)
    const uint32_t bRow = (uint32_t)(nh + (mi >> 1) * 8 + rowin) * ROWB + (uint32_t)(mi & 1) * 16;

    // gather task: thread -> (p, q), q = 4-channel group
    const int gp = t >> 2, gq = t & 3;

    float acc[8][4];
#pragma unroll
    for (int i = 0; i < 8; i++)
#pragma unroll
        for (int j = 0; j < 4; j++) acc[i][j] = 0.0f;

    for (int ch = 0; ch < NCHUNK; ch++) {
        __syncthreads();   // prev-chunk MMAs done reading tiles (also covers idxs/bias on ch=0)

        // ---- fill B tiles (plain copy of pre-split images) ----
        {
            const uint4* shi = (const uint4*)&g_Wbf[0][ch][0][0];
            const uint4* slo = (const uint4*)&g_Wbf[1][ch][0][0];
            uint4* dhi = (uint4*)(sm + OFF_BHI);
            uint4* dlo = (uint4*)(sm + OFF_BLO);
            for (int i = t; i < TILE_B / 16; i += NTHREADS) { dhi[i] = shi[i]; dlo[i] = slo[i]; }
        }

        // ---- gather + features + bf16 split -> A tiles ----
        {
            const int cbase = ch * 16 + gq * 4;
            const float4 z4 = make_float4(0.f, 0.f, 0.f, 0.f);
            int r0 = idxs[gp * 4 + 0], r1 = idxs[gp * 4 + 1];
            int r2 = idxs[gp * 4 + 2], r3 = idxs[gp * 4 + 3];
            float4 v0 = (r0 >= 0) ? *(const float4*)&g_xT[(size_t)r0 * CIN + cbase] : z4;
            float4 v1 = (r1 >= 0) ? *(const float4*)&g_xT[(size_t)r1 * CIN + cbase] : z4;
            float4 v2 = (r2 >= 0) ? *(const float4*)&g_xT[(size_t)r2 * CIN + cbase] : z4;
            float4 v3 = (r3 >= 0) ? *(const float4*)&g_xT[(size_t)r3 * CIN + cbase] : z4;
            const float a0[4] = {v0.x, v0.y, v0.z, v0.w};
            const float a1[4] = {v1.x, v1.y, v1.z, v1.w};
            const float a2[4] = {v2.x, v2.y, v2.z, v2.w};
            const float a3[4] = {v3.x, v3.y, v3.z, v3.w};
            uint32_t hw[NK][2], lw[NK][2];
#pragma unroll
            for (int r = 0; r < NK; r++) { hw[r][0] = hw[r][1] = lw[r][0] = lw[r][1] = 0u; }
#pragma unroll
            for (int ci = 0; ci < 4; ci++) {
                float f0 = a0[ci], f1 = a1[ci], f2 = a2[ci], f3 = a3[ci];
                float p12 = f1 * f2, p13 = f1 * f3, p23 = f2 * f3;
                float s[NK];
                s[0] = f0;
                s[1] = f1 + f2 + f3;
                s[2] = p12 * f3;
                s[3] = p12 + p13 + p23;
                s[4] = f1 * f1 + f2 * f2 + f3 * f3;
                s[5] = fabsf(f1 - f2) + fabsf(f1 - f3) + fabsf(f2 - f3);
                s[6] = f1 * f1 * f1 + f2 * f2 * f2 + f3 * f3 * f3;
                const int wsel = ci >> 1, shf = (ci & 1) * 16;
#pragma unroll
                for (int r = 0; r < NK; r++) {
                    uint32_t h, l;
                    bsplit(s[r], h, l);
                    hw[r][wsel] |= h << shf;
                    lw[r][wsel] |= l << shf;
                }
            }
            char* Ah = sm + OFF_AHI + gp * ROWB + gq * 8;
            char* Al = sm + OFF_ALO + gp * ROWB + gq * 8;
#pragma unroll
            for (int r = 0; r < NK; r++) {
                *(uint2*)(Ah + r * 32) = make_uint2(hw[r][0], hw[r][1]);
                *(uint2*)(Al + r * 32) = make_uint2(lw[r][0], lw[r][1]);
            }
        }
        __syncthreads();

        // ---- MMA phase: 7 k16-steps ----
#pragma unroll
        for (int ks = 0; ks < 7; ks++) {
            const uint32_t kb = (uint32_t)ks * 32;
            uint32_t ah0, ah1, ah2, ah3, al0, al1, al2, al3;
            LDMX4(ah0, ah1, ah2, ah3, sb + OFF_AHI + aOff + kb);
            LDMX4(al0, al1, al2, al3, sb + OFF_ALO + aOff + kb);
#pragma unroll
            for (int ntp = 0; ntp < 4; ntp++) {
                const uint32_t bo = bRow + (uint32_t)ntp * 16 * ROWB + kb;
                uint32_t bh0, bh1, bh2, bh3, bl0, bl1, bl2, bl3;
                LDMX4(bh0, bh1, bh2, bh3, sb + OFF_BHI + bo);
                LDMX4(bl0, bl1, bl2, bl3, sb + OFF_BLO + bo);
                MMA16816(acc[2 * ntp],     ah0, ah1, ah2, ah3, bh0, bh1);
                MMA16816(acc[2 * ntp],     al0, al1, al2, al3, bh0, bh1);
                MMA16816(acc[2 * ntp],     ah0, ah1, ah2, ah3, bl0, bl1);
                MMA16816(acc[2 * ntp + 1], ah0, ah1, ah2, ah3, bh2, bh3);
                MMA16816(acc[2 * ntp + 1], al0, al1, al2, al3, bh2, bh3);
                MMA16816(acc[2 * ntp + 1], ah0, ah1, ah2, ah3, bl2, bl3);
            }
        }
    }
    __syncthreads();   // last MMAs done; overlay sOut on tile region

    // ---- epilogue: d-frags -> sOut[p][o], then coalesced global stores ----
    float* sOut = (float*)sm;          // [128][SOUT_PITCH]
    {
        const int prow = mb + (lane >> 2);
        const int ncol = nh + 2 * (lane & 3);
#pragma unroll
        for (int nt = 0; nt < 8; nt++) {
            const int n = ncol + nt * 8;
            *(float2*)&sOut[prow * SOUT_PITCH + n]       = make_float2(acc[nt][0], acc[nt][1]);
            *(float2*)&sOut[(prow + 8) * SOUT_PITCH + n] = make_float2(acc[nt][2], acc[nt][3]);
        }
    }
    __syncthreads();

    for (int idx = t; idx < COUT * TP; idx += NTHREADS) {
        int o  = idx >> 7;
        int vl = idx & 127;
        int pg = p0 + vl;
        if (pg < NPTS) {
            int b = pg / NV;
            int v = pg - b * NV;
            out[((size_t)(b * COUT + o)) * NV + v] = sOut[vl * SOUT_PITCH + o] + sBias[o];
        }
    }
}

extern "C" void kernel_launch(void* const* d_in, const int* in_sizes, int n_in,
                              void* d_out, int out_size) {
    const float* x    = (const float*)d_in[0];      // [B, C_IN, V, 1]
    const int*   Gi   = (const int*)d_in[1];        // [B, V, 4] (int32/int64 probed)
    const float* W    = (const float*)d_in[2];      // [C_OUT, C_IN, 7]
    const float* bias = (const float*)d_in[3];      // [C_OUT]
    float*       out  = (float*)d_out;              // [B, C_OUT, V, 1]

    static bool attr_set = false;
    if (!attr_set) {
        cudaFuncSetAttribute(mesh_main,
                             cudaFuncAttributeMaxDynamicSharedMemorySize,
                             SMEM_TOTAL);
        attr_set = true;
    }

    transpose_kernel<<<dim3((NV + 31) / 32, CIN / 32, BATCH), dim3(32, 8)>>>(x);
    wprep_kernel<<<(NCHUNK * 128 * 120 + 255) / 256, 256>>>(W);
    mesh_main<<<NTILES, NTHREADS, SMEM_TOTAL>>>(Gi, bias, out);
}

// round 11
// speedup vs baseline: 2.4352x; 1.1418x over previous
#include <cuda_runtime.h>
#include <cuda_bf16.h>
#include <cstdint>

// MeshConvPoint via warp-level mma.sync (bf16 HMMA), software-pipelined.
//   out[pts,128] = G[pts,448] @ W[448,128] + bias, fused with gather.
//   3-term split precision: D ~= Ah*Bh + Al*Bh + Ah*Bl (fp32 accum).
//
// CTA: 128 points x 128 outputs, 512 threads = 16 warps, warp tile m32n32.
// K = 448 = 4 chunks x 112 (7 k16-steps each), k_local = r*16 + c.
// Pipeline: cp.async gather (next chunk) + cp.async B copy overlap the
// MMA phase / feature ALU. A tiles double-buffered, B single-buffered.

#define BATCH    4
#define CIN      64
#define NV       50000
#define COUT     128
#define NK       7
#define CK       (CIN * NK)              // 448
#define NPTS     (BATCH * NV)            // 200000
#define TP       128
#define NTILES   ((NPTS + TP - 1) / TP)  // 1563
#define NTHREADS 512
#define NCHUNK   4
#define KCHUNK   112
#define ROWB     240                     // padded row bytes (120 bf16)
#define TILE_B   (128 * ROWB)            // 30720

// smem layout (bytes)
#define OFF_A    0                        // [2 stage][2 term][TILE_B] = 122880
#define OFF_B    (4 * TILE_B)             // 122880: [2 term][TILE_B] = 61440
#define OFF_GRAW (OFF_B + 2 * TILE_B)     // 184320: [4][512][16] = 32768
#define OFF_BIAS (OFF_GRAW + 32768)       // 217088: 128 floats
#define SMEM_TOTAL (OFF_BIAS + 512)       // 217600
#define SOUT_PITCH 132                    // epilogue overlay [128][132] f32

// static scratch
__device__ __align__(16) float         g_xT[(size_t)BATCH * NV * CIN];   // 51.2 MB
__device__ __align__(16) __nv_bfloat16 g_Wbf[NCHUNK][2][128][120];       // pre-split W

__device__ __forceinline__ uint32_t smem_u32(const void* p) {
    uint32_t a;
    asm("{ .reg .u64 t; cvta.to.shared.u64 t, %1; cvt.u32.u64 %0, t; }" : "=r"(a) : "l"(p));
    return a;
}
__device__ __forceinline__ void bsplit(float v, uint32_t& h, uint32_t& l) {
    __nv_bfloat16 hb = __float2bfloat16(v);
    h = (uint32_t)__bfloat16_as_ushort(hb);
    float hf = __uint_as_float(h << 16);            // exact bf16 -> f32
    l = (uint32_t)__bfloat16_as_ushort(__float2bfloat16(v - hf));
}

#define LDMX4(r0, r1, r2, r3, addr) \
    asm volatile("ldmatrix.sync.aligned.m8n8.x4.shared.b16 {%0,%1,%2,%3}, [%4];" \
                 : "=r"(r0), "=r"(r1), "=r"(r2), "=r"(r3) : "r"(addr))

#define MMA16816(d, a0, a1, a2, a3, b0, b1) \
    asm volatile("mma.sync.aligned.m16n8k16.row.col.f32.bf16.bf16.f32 " \
                 "{%0,%1,%2,%3}, {%4,%5,%6,%7}, {%8,%9}, {%0,%1,%2,%3};" \
                 : "+f"((d)[0]), "+f"((d)[1]), "+f"((d)[2]), "+f"((d)[3]) \
                 : "r"(a0), "r"(a1), "r"(a2), "r"(a3), "r"(b0), "r"(b1))

#define CPA16(dst, src, sz) \
    asm volatile("cp.async.cg.shared.global [%0], [%1], 16, %2;" \
                 :: "r"(dst), "l"(src), "r"(sz))
#define CPCOMMIT() asm volatile("cp.async.commit_group;" ::: "memory")
#define CPWAIT0()  asm volatile("cp.async.wait_group 0;" ::: "memory")
#define CPWAIT1()  asm volatile("cp.async.wait_group 1;" ::: "memory")

// ---- 1) transpose x [B,C,V] -> xT [B,V,C] ----
__global__ void transpose_kernel(const float* __restrict__ x) {
    __shared__ float tile[32][33];
    int b  = blockIdx.z;
    int cb = blockIdx.y * 32;
    int vb = blockIdx.x * 32;
    int tx = threadIdx.x, ty = threadIdx.y;
#pragma unroll
    for (int i = 0; i < 32; i += 8) {
        int c = cb + ty + i, v = vb + tx;
        if (v < NV) tile[ty + i][tx] = x[((size_t)(b * CIN + c)) * NV + v];
    }
    __syncthreads();
#pragma unroll
    for (int i = 0; i < 32; i += 8) {
        int v = vb + ty + i, c = cb + tx;
        if (v < NV) g_xT[((size_t)(b * NV + v)) * CIN + c] = tile[tx][ty + i];
    }
}

// ---- 2) W -> bf16 hi/lo tiles [chunk][term][n=128][k=120], k = r*16 + c ----
__global__ void wprep_kernel(const float* __restrict__ W) {
    int i = blockIdx.x * 256 + threadIdx.x;         // over 4*128*120 = 61440
    if (i >= NCHUNK * 128 * 120) return;
    int kl = i % 120;
    int n  = (i / 120) & 127;
    int ch = i / (120 * 128);
    uint32_t h = 0, l = 0;
    if (kl < KCHUNK) {
        int r = kl >> 4, c = kl & 15;
        float v = W[n * CK + (ch * 16 + c) * NK + r];
        bsplit(v, h, l);
    }
    g_Wbf[ch][0][n][kl] = __ushort_as_bfloat16((unsigned short)h);
    g_Wbf[ch][1][n][kl] = __ushort_as_bfloat16((unsigned short)l);
}

// ---- 3) fused pipelined main kernel ----
__global__ void __launch_bounds__(NTHREADS, 1)
mesh_main(const int* __restrict__ Gi32,
          const float* __restrict__ bias,
          float* __restrict__ out) {
    extern __shared__ char sm[];
    const uint32_t sb = smem_u32(sm);
    const int t    = threadIdx.x;
    const int wid  = t >> 5;
    const int lane = t & 31;
    const int p0   = blockIdx.x * TP;

    float* sBias = (float*)(sm + OFF_BIAS);
    if (t < COUT) sBias[t] = bias[t];

    // per-thread gather task: point gp, 4-channel group gq
    const int gp = t >> 2, gq = t & 3;

    // resolve this thread's 4 neighbor rows (L1-broadcast loads, no smem)
    int rows[4];
    {
        bool is64 = ((Gi32[1] | Gi32[3] | Gi32[5] | Gi32[7]) == 0);
        int pg = p0 + gp;
#pragma unroll
        for (int j = 0; j < 4; j++) {
            int row = -1;
            if (pg < NPTS) {
                int raw = is64 ? Gi32[2 * (pg * 4 + j)] : Gi32[pg * 4 + j];
                if (raw >= 0 && raw < NV) row = (pg / NV) * NV + raw;
            }
            rows[j] = row;
        }
    }

    // warp MMA tiling: 4x4 warps of m32 x n32
    const int mb = (wid & 3) * 32;
    const int nb = (wid >> 2) * 32;
    const int mi = lane >> 3, rowin = lane & 7;
    const uint32_t aOff = (uint32_t)(mb + (mi & 1) * 8 + rowin) * ROWB + (uint32_t)(mi >> 1) * 16;
    const uint32_t bOff = (uint32_t)(nb + (mi >> 1) * 8 + rowin) * ROWB + (uint32_t)(mi & 1) * 16;

    float acc[2][4][4];
#pragma unroll
    for (int a = 0; a < 2; a++)
#pragma unroll
        for (int b = 0; b < 4; b++)
#pragma unroll
            for (int c = 0; c < 4; c++) acc[a][b][c] = 0.0f;

    // gather staging: [j][512][16B] -> conflict-free LDS.128 readback
    auto issue_gather = [&](int ch) {
#pragma unroll
        for (int j = 0; j < 4; j++) {
            const char* src = (const char*)(g_xT +
                ((rows[j] >= 0) ? (size_t)rows[j] * CIN : 0) + (ch * 16 + gq * 4));
            CPA16(sb + OFF_GRAW + (uint32_t)(j * NTHREADS + t) * 16, src,
                  rows[j] >= 0 ? 16u : 0u);
        }
        CPCOMMIT();
    };

    issue_gather(0);                      // prologue

    for (int ch = 0; ch < NCHUNK; ch++) {
        const int stage = ch & 1;

        // B copy (cp.async; overlaps gather wait + feature ALU)
        {
            const char* bsrc = (const char*)&g_Wbf[ch][0][0][0];   // 61440B contiguous
            for (int i = t; i < (2 * TILE_B) / 16; i += NTHREADS)
                CPA16(sb + OFF_B + (uint32_t)i * 16, bsrc + (size_t)i * 16, 16u);
            CPCOMMIT();
        }
        CPWAIT1();                        // gather(ch) landed; B(ch) still in flight

        // features: read staging, compute, bf16-split, STS -> A[stage]
        {
            float4 v[4];
#pragma unroll
            for (int j = 0; j < 4; j++) {
                uint32_t a = sb + OFF_GRAW + (uint32_t)(j * NTHREADS + t) * 16;
                asm volatile("ld.shared.v4.f32 {%0,%1,%2,%3}, [%4];"
                             : "=f"(v[j].x), "=f"(v[j].y), "=f"(v[j].z), "=f"(v[j].w)
                             : "r"(a));
            }
            const float a0[4] = {v[0].x, v[0].y, v[0].z, v[0].w};
            const float a1[4] = {v[1].x, v[1].y, v[1].z, v[1].w};
            const float a2[4] = {v[2].x, v[2].y, v[2].z, v[2].w};
            const float a3[4] = {v[3].x, v[3].y, v[3].z, v[3].w};
            uint32_t hw[NK][2], lw[NK][2];
#pragma unroll
            for (int r = 0; r < NK; r++) { hw[r][0] = hw[r][1] = lw[r][0] = lw[r][1] = 0u; }
#pragma unroll
            for (int ci = 0; ci < 4; ci++) {
                float f0 = a0[ci], f1 = a1[ci], f2 = a2[ci], f3 = a3[ci];
                float p12 = f1 * f2, p13 = f1 * f3, p23 = f2 * f3;
                float s[NK];
                s[0] = f0;
                s[1] = f1 + f2 + f3;
                s[2] = p12 * f3;
                s[3] = p12 + p13 + p23;
                s[4] = f1 * f1 + f2 * f2 + f3 * f3;
                s[5] = fabsf(f1 - f2) + fabsf(f1 - f3) + fabsf(f2 - f3);
                s[6] = f1 * f1 * f1 + f2 * f2 * f2 + f3 * f3 * f3;
                const int wsel = ci >> 1, shf = (ci & 1) * 16;
#pragma unroll
                for (int r = 0; r < NK; r++) {
                    uint32_t h, l;
                    bsplit(s[r], h, l);
                    hw[r][wsel] |= h << shf;
                    lw[r][wsel] |= l << shf;
                }
            }
            char* Ah = sm + OFF_A + stage * (2 * TILE_B) + gp * ROWB + gq * 8;
            char* Al = Ah + TILE_B;
#pragma unroll
            for (int r = 0; r < NK; r++) {
                *(uint2*)(Ah + r * 32) = make_uint2(hw[r][0], hw[r][1]);
                *(uint2*)(Al + r * 32) = make_uint2(lw[r][0], lw[r][1]);
            }
        }

        // prefetch next chunk's gather (hides under the MMA phase)
        if (ch < NCHUNK - 1) { issue_gather(ch + 1); CPWAIT1(); }   // waits B(ch)
        else                 { CPWAIT0(); }                          // waits B(3)

        __syncthreads();   // A[stage] + B visible; prev MMA already done (loop-end sync)

        // MMA phase: 7 k16-steps, warp tile m32 x n32
        const uint32_t Ab = sb + OFF_A + (uint32_t)stage * (2 * TILE_B);
        const uint32_t Bb = sb + OFF_B;
#pragma unroll
        for (int ks = 0; ks < 7; ks++) {
            const uint32_t kb = (uint32_t)ks * 32;
            uint32_t ah0, ah1, ah2, ah3, ah4, ah5, ah6, ah7;
            uint32_t al0, al1, al2, al3, al4, al5, al6, al7;
            LDMX4(ah0, ah1, ah2, ah3, Ab + aOff + kb);
            LDMX4(ah4, ah5, ah6, ah7, Ab + aOff + 16 * ROWB + kb);
            LDMX4(al0, al1, al2, al3, Ab + TILE_B + aOff + kb);
            LDMX4(al4, al5, al6, al7, Ab + TILE_B + aOff + 16 * ROWB + kb);
            uint32_t bh0, bh1, bh2, bh3, bh4, bh5, bh6, bh7;
            uint32_t bl0, bl1, bl2, bl3, bl4, bl5, bl6, bl7;
            LDMX4(bh0, bh1, bh2, bh3, Bb + bOff + kb);
            LDMX4(bh4, bh5, bh6, bh7, Bb + bOff + 16 * ROWB + kb);
            LDMX4(bl0, bl1, bl2, bl3, Bb + TILE_B + bOff + kb);
            LDMX4(bl4, bl5, bl6, bl7, Bb + TILE_B + bOff + 16 * ROWB + kb);

            MMA16816(acc[0][0], ah0, ah1, ah2, ah3, bh0, bh1);
            MMA16816(acc[0][0], al0, al1, al2, al3, bh0, bh1);
            MMA16816(acc[0][0], ah0, ah1, ah2, ah3, bl0, bl1);
            MMA16816(acc[0][1], ah0, ah1, ah2, ah3, bh2, bh3);
            MMA16816(acc[0][1], al0, al1, al2, al3, bh2, bh3);
            MMA16816(acc[0][1], ah0, ah1, ah2, ah3, bl2, bl3);
            MMA16816(acc[0][2], ah0, ah1, ah2, ah3, bh4, bh5);
            MMA16816(acc[0][2], al0, al1, al2, al3, bh4, bh5);
            MMA16816(acc[0][2], ah0, ah1, ah2, ah3, bl4, bl5);
            MMA16816(acc[0][3], ah0, ah1, ah2, ah3, bh6, bh7);
            MMA16816(acc[0][3], al0, al1, al2, al3, bh6, bh7);
            MMA16816(acc[0][3], ah0, ah1, ah2, ah3, bl6, bl7);

            MMA16816(acc[1][0], ah4, ah5, ah6, ah7, bh0, bh1);
            MMA16816(acc[1][0], al4, al5, al6, al7, bh0, bh1);
            MMA16816(acc[1][0], ah4, ah5, ah6, ah7, bl0, bl1);
            MMA16816(acc[1][1], ah4, ah5, ah6, ah7, bh2, bh3);
            MMA16816(acc[1][1], al4, al5, al6, al7, bh2, bh3);
            MMA16816(acc[1][1], ah4, ah5, ah6, ah7, bl2, bl3);
            MMA16816(acc[1][2], ah4, ah5, ah6, ah7, bh4, bh5);
            MMA16816(acc[1][2], al4, al5, al6, al7, bh4, bh5);
            MMA16816(acc[1][2], ah4, ah5, ah6, ah7, bl4, bl5);
            MMA16816(acc[1][3], ah4, ah5, ah6, ah7, bh6, bh7);
            MMA16816(acc[1][3], al4, al5, al6, al7, bh6, bh7);
            MMA16816(acc[1][3], ah4, ah5, ah6, ah7, bl6, bl7);
        }
        __syncthreads();   // MMA done before next B overwrite / A-stage reuse
    }

    // ---- epilogue: d-frags -> sOut[p][o], then coalesced global stores ----
    float* sOut = (float*)sm;          // [128][SOUT_PITCH] overlay on A tiles
    {
        const int r4 = lane >> 2, c2 = 2 * (lane & 3);
#pragma unroll
        for (int mt = 0; mt < 2; mt++) {
            const int prow = mb + mt * 16 + r4;
#pragma unroll
            for (int ng = 0; ng < 4; ng++) {
                const int n = nb + ng * 8 + c2;
                *(float2*)&sOut[prow * SOUT_PITCH + n] =
                    make_float2(acc[mt][ng][0], acc[mt][ng][1]);
                *(float2*)&sOut[(prow + 8) * SOUT_PITCH + n] =
                    make_float2(acc[mt][ng][2], acc[mt][ng][3]);
            }
        }
    }
    __syncthreads();

    for (int idx = t; idx < COUT * TP; idx += NTHREADS) {
        int o  = idx >> 7;
        int vl = idx & 127;
        int pg = p0 + vl;
        if (pg < NPTS) {
            int b = pg / NV;
            int v = pg - b * NV;
            out[((size_t)(b * COUT + o)) * NV + v] = sOut[vl * SOUT_PITCH + o] + sBias[o];
        }
    }
}

extern "C" void kernel_launch(void* const* d_in, const int* in_sizes, int n_in,
                              void* d_out, int out_size) {
    const float* x    = (const float*)d_in[0];      // [B, C_IN, V, 1]
    const int*   Gi   = (const int*)d_in[1];        // [B, V, 4] (int32/int64 probed)
    const float* W    = (const float*)d_in[2];      // [C_OUT, C_IN, 7]
    const float* bias = (const float*)d_in[3];      // [C_OUT]
    float*       out  = (float*)d_out;              // [B, C_OUT, V, 1]

    static bool attr_set = false;
    if (!attr_set) {
        cudaFuncSetAttribute(mesh_main,
                             cudaFuncAttributeMaxDynamicSharedMemorySize,
                             SMEM_TOTAL);
        attr_set = true;
    }

    transpose_kernel<<<dim3((NV + 31) / 32, CIN / 32, BATCH), dim3(32, 8)>>>(x);
    wprep_kernel<<<(NCHUNK * 128 * 120 + 255) / 256, 256>>>(W);
    mesh_main<<<NTILES, NTHREADS, SMEM_TOTAL>>>(Gi, bias, out);
}

// round 13
// speedup vs baseline: 3.9549x; 1.6241x over previous
#include <cuda_runtime.h>
#include <cuda_fp16.h>
#include <cstdint>

// MeshConvPoint via warp-level mma.sync (fp16 HMMA, single-pass), pipelined.
//   out[pts,128] = G[pts,448] @ W[448,128] + bias, fused with gather.
//   fp16 operands (11-bit mantissa), fp32 accumulation: rel_err ~2e-4 global.
//
// CTA: 128 points x 128 outputs, 512 threads = 16 warps, warp tile m32n32.
// K = 448 = 4 chunks x 112 (7 k16-steps each), k_local = r*16 + c.
// Pipeline: cp.async gather (next chunk) + cp.async B copy overlap the MMA
// phase / feature ALU. A tiles double-buffered, B single-buffered.

#define BATCH    4
#define CIN      64
#define NV       50000
#define COUT     128
#define NK       7
#define CK       (CIN * NK)              // 448
#define NPTS     (BATCH * NV)            // 200000
#define TP       128
#define NTILES   ((NPTS + TP - 1) / TP)  // 1563
#define NTHREADS 512
#define NCHUNK   4
#define KCHUNK   112
#define ROWB     240                     // padded row bytes (120 fp16)
#define TILE_B   (128 * ROWB)            // 30720

// smem layout (bytes)
#define OFF_A    0                        // [2 stage][TILE_B] = 61440
#define OFF_B    (2 * TILE_B)             // 61440: TILE_B = 30720
#define OFF_GRAW (3 * TILE_B)             // 92160: [4][512][16] = 32768
#define OFF_BIAS (OFF_GRAW + 32768)       // 124928: 128 floats
#define SMEM_TOTAL (OFF_BIAS + 512)       // 125440
#define SOUT_PITCH 132                    // epilogue overlay [128][132] f32

// static scratch
__device__ __align__(16) float  g_xT[(size_t)BATCH * NV * CIN];   // 51.2 MB
__device__ __align__(16) __half g_Whf[NCHUNK][128][120];          // fp16 W tiles

__device__ __forceinline__ uint32_t smem_u32(const void* p) {
    uint32_t a;
    asm("{ .reg .u64 t; cvta.to.shared.u64 t, %1; cvt.u32.u64 %0, t; }" : "=r"(a) : "l"(p));
    return a;
}

#define LDMX4(r0, r1, r2, r3, addr) \
    asm volatile("ldmatrix.sync.aligned.m8n8.x4.shared.b16 {%0,%1,%2,%3}, [%4];" \
                 : "=r"(r0), "=r"(r1), "=r"(r2), "=r"(r3) : "r"(addr))

#define MMA16816(d, a0, a1, a2, a3, b0, b1) \
    asm volatile("mma.sync.aligned.m16n8k16.row.col.f32.f16.f16.f32 " \
                 "{%0,%1,%2,%3}, {%4,%5,%6,%7}, {%8,%9}, {%0,%1,%2,%3};" \
                 : "+f"((d)[0]), "+f"((d)[1]), "+f"((d)[2]), "+f"((d)[3]) \
                 : "r"(a0), "r"(a1), "r"(a2), "r"(a3), "r"(b0), "r"(b1))

#define CPA16(dst, src, sz) \
    asm volatile("cp.async.cg.shared.global [%0], [%1], 16, %2;" \
                 :: "r"(dst), "l"(src), "r"(sz))
#define CPCOMMIT() asm volatile("cp.async.commit_group;" ::: "memory")
#define CPWAIT0()  asm volatile("cp.async.wait_group 0;" ::: "memory")
#define CPWAIT1()  asm volatile("cp.async.wait_group 1;" ::: "memory")

// ---- 1) transpose x [B,C,V] -> xT [B,V,C] ----
__global__ void transpose_kernel(const float* __restrict__ x) {
    __shared__ float tile[32][33];
    int b  = blockIdx.z;
    int cb = blockIdx.y * 32;
    int vb = blockIdx.x * 32;
    int tx = threadIdx.x, ty = threadIdx.y;
#pragma unroll
    for (int i = 0; i < 32; i += 8) {
        int c = cb + ty + i, v = vb + tx;
        if (v < NV) tile[ty + i][tx] = x[((size_t)(b * CIN + c)) * NV + v];
    }
    __syncthreads();
#pragma unroll
    for (int i = 0; i < 32; i += 8) {
        int v = vb + ty + i, c = cb + tx;
        if (v < NV) g_xT[((size_t)(b * NV + v)) * CIN + c] = tile[tx][ty + i];
    }
}

// ---- 2) W -> fp16 tiles [chunk][n=128][k=120], k = r*16 + c ----
__global__ void wprep_kernel(const float* __restrict__ W) {
    int i = blockIdx.x * 256 + threadIdx.x;         // over 4*128*120 = 61440
    if (i >= NCHUNK * 128 * 120) return;
    int kl = i % 120;
    int n  = (i / 120) & 127;
    int ch = i / (120 * 128);
    float v = 0.0f;
    if (kl < KCHUNK) {
        int r = kl >> 4, c = kl & 15;
        v = W[n * CK + (ch * 16 + c) * NK + r];
    }
    g_Whf[ch][n][kl] = __float2half_rn(v);
}

// ---- 3) fused pipelined main kernel ----
__global__ void __launch_bounds__(NTHREADS, 1)
mesh_main(const int* __restrict__ Gi32,
          const float* __restrict__ bias,
          float* __restrict__ out) {
    extern __shared__ char sm[];
    const uint32_t sb = smem_u32(sm);
    const int t    = threadIdx.x;
    const int wid  = t >> 5;
    const int lane = t & 31;
    const int p0   = blockIdx.x * TP;

    float* sBias = (float*)(sm + OFF_BIAS);
    if (t < COUT) sBias[t] = bias[t];

    // per-thread gather task: point gp, 4-channel group gq
    const int gp = t >> 2, gq = t & 3;

    // resolve this thread's 4 neighbor rows (L1-broadcast loads, no smem)
    int rows[4];
    {
        bool is64 = ((Gi32[1] | Gi32[3] | Gi32[5] | Gi32[7]) == 0);
        int pg = p0 + gp;
#pragma unroll
        for (int j = 0; j < 4; j++) {
            int row = -1;
            if (pg < NPTS) {
                int raw = is64 ? Gi32[2 * (pg * 4 + j)] : Gi32[pg * 4 + j];
                if (raw >= 0 && raw < NV) row = (pg / NV) * NV + raw;
            }
            rows[j] = row;
        }
    }

    // warp MMA tiling: 4x4 warps of m32 x n32
    const int mb = (wid & 3) * 32;
    const int nb = (wid >> 2) * 32;
    const int mi = lane >> 3, rowin = lane & 7;
    const uint32_t aOff = (uint32_t)(mb + (mi & 1) * 8 + rowin) * ROWB + (uint32_t)(mi >> 1) * 16;
    const uint32_t bOff = (uint32_t)(nb + (mi >> 1) * 8 + rowin) * ROWB + (uint32_t)(mi & 1) * 16;

    float acc[2][4][4];
#pragma unroll
    for (int a = 0; a < 2; a++)
#pragma unroll
        for (int b = 0; b < 4; b++)
#pragma unroll
            for (int c = 0; c < 4; c++) acc[a][b][c] = 0.0f;

    // gather staging: [j][512][16B] -> conflict-free LDS.128 readback
    auto issue_gather = [&](int ch) {
#pragma unroll
        for (int j = 0; j < 4; j++) {
            const char* src = (const char*)(g_xT +
                ((rows[j] >= 0) ? (size_t)rows[j] * CIN : 0) + (ch * 16 + gq * 4));
            CPA16(sb + OFF_GRAW + (uint32_t)(j * NTHREADS + t) * 16, src,
                  rows[j] >= 0 ? 16u : 0u);
        }
        CPCOMMIT();
    };

    issue_gather(0);                      // prologue

    for (int ch = 0; ch < NCHUNK; ch++) {
        const int stage = ch & 1;

        // B copy (cp.async; overlaps gather wait + feature ALU)
        {
            const char* bsrc = (const char*)&g_Whf[ch][0][0];   // 30720B contiguous
            for (int i = t; i < TILE_B / 16; i += NTHREADS)
                CPA16(sb + OFF_B + (uint32_t)i * 16, bsrc + (size_t)i * 16, 16u);
            CPCOMMIT();
        }
        CPWAIT1();                        // gather(ch) landed; B(ch) still in flight

        // features: read staging, compute, fp16 convert, STS -> A[stage]
        {
            float4 v[4];
#pragma unroll
            for (int j = 0; j < 4; j++) {
                uint32_t a = sb + OFF_GRAW + (uint32_t)(j * NTHREADS + t) * 16;
                asm volatile("ld.shared.v4.f32 {%0,%1,%2,%3}, [%4];"
                             : "=f"(v[j].x), "=f"(v[j].y), "=f"(v[j].z), "=f"(v[j].w)
                             : "r"(a));
            }
            const float a0[4] = {v[0].x, v[0].y, v[0].z, v[0].w};
            const float a1[4] = {v[1].x, v[1].y, v[1].z, v[1].w};
            const float a2[4] = {v[2].x, v[2].y, v[2].z, v[2].w};
            const float a3[4] = {v[3].x, v[3].y, v[3].z, v[3].w};
            uint32_t hw[NK][2];
#pragma unroll
            for (int r = 0; r < NK; r++) { hw[r][0] = hw[r][1] = 0u; }
#pragma unroll
            for (int ci = 0; ci < 4; ci++) {
                float f0 = a0[ci], f1 = a1[ci], f2 = a2[ci], f3 = a3[ci];
                float p12 = f1 * f2, p13 = f1 * f3, p23 = f2 * f3;
                float s[NK];
                s[0] = f0;
                s[1] = f1 + f2 + f3;
                s[2] = p12 * f3;
                s[3] = p12 + p13 + p23;
                s[4] = f1 * f1 + f2 * f2 + f3 * f3;
                s[5] = fabsf(f1 - f2) + fabsf(f1 - f3) + fabsf(f2 - f3);
                s[6] = f1 * f1 * f1 + f2 * f2 * f2 + f3 * f3 * f3;
                const int wsel = ci >> 1, shf = (ci & 1) * 16;
#pragma unroll
                for (int r = 0; r < NK; r++) {
                    uint32_t h = (uint32_t)__half_as_ushort(__float2half_rn(s[r]));
                    hw[r][wsel] |= h << shf;
                }
            }
            char* Ah = sm + OFF_A + stage * TILE_B + gp * ROWB + gq * 8;
#pragma unroll
            for (int r = 0; r < NK; r++)
                *(uint2*)(Ah + r * 32) = make_uint2(hw[r][0], hw[r][1]);
        }

        // prefetch next chunk's gather (hides under the MMA phase)
        if (ch < NCHUNK - 1) { issue_gather(ch + 1); CPWAIT1(); }   // waits B(ch)
        else                 { CPWAIT0(); }                          // waits B(3)

        __syncthreads();   // A[stage] + B visible; prev MMA already done (loop-end sync)

        // MMA phase: 7 k16-steps, warp tile m32 x n32
        const uint32_t Ab = sb + OFF_A + (uint32_t)stage * TILE_B;
        const uint32_t Bb = sb + OFF_B;
#pragma unroll
        for (int ks = 0; ks < 7; ks++) {
            const uint32_t kb = (uint32_t)ks * 32;
            uint32_t a0, a1, a2, a3, a4, a5, a6, a7;
            LDMX4(a0, a1, a2, a3, Ab + aOff + kb);
            LDMX4(a4, a5, a6, a7, Ab + aOff + 16 * ROWB + kb);
            uint32_t b0, b1, b2, b3, b4, b5, b6, b7;
            LDMX4(b0, b1, b2, b3, Bb + bOff + kb);
            LDMX4(b4, b5, b6, b7, Bb + bOff + 16 * ROWB + kb);

            MMA16816(acc[0][0], a0, a1, a2, a3, b0, b1);
            MMA16816(acc[0][1], a0, a1, a2, a3, b2, b3);
            MMA16816(acc[0][2], a0, a1, a2, a3, b4, b5);
            MMA16816(acc[0][3], a0, a1, a2, a3, b6, b7);
            MMA16816(acc[1][0], a4, a5, a6, a7, b0, b1);
            MMA16816(acc[1][1], a4, a5, a6, a7, b2, b3);
            MMA16816(acc[1][2], a4, a5, a6, a7, b4, b5);
            MMA16816(acc[1][3], a4, a5, a6, a7, b6, b7);
        }
        __syncthreads();   // MMA done before next B overwrite / A-stage reuse
    }

    // ---- epilogue: d-frags -> sOut[p][o], then coalesced global stores ----
    float* sOut = (float*)sm;          // [128][SOUT_PITCH] overlay on A/B tiles
    {
        const int r4 = lane >> 2, c2 = 2 * (lane & 3);
#pragma unroll
        for (int mt = 0; mt < 2; mt++) {
            const int prow = mb + mt * 16 + r4;
#pragma unroll
            for (int ng = 0; ng < 4; ng++) {
                const int n = nb + ng * 8 + c2;
                *(float2*)&sOut[prow * SOUT_PITCH + n] =
                    make_float2(acc[mt][ng][0], acc[mt][ng][1]);
                *(float2*)&sOut[(prow + 8) * SOUT_PITCH + n] =
                    make_float2(acc[mt][ng][2], acc[mt][ng][3]);
            }
        }
    }
    __syncthreads();

    for (int idx = t; idx < COUT * TP; idx += NTHREADS) {
        int o  = idx >> 7;
        int vl = idx & 127;
        int pg = p0 + vl;
        if (pg < NPTS) {
            int b = pg / NV;
            int v = pg - b * NV;
            out[((size_t)(b * COUT + o)) * NV + v] = sOut[vl * SOUT_PITCH + o] + sBias[o];
        }
    }
}

extern "C" void kernel_launch(void* const* d_in, const int* in_sizes, int n_in,
                              void* d_out, int out_size) {
    const float* x    = (const float*)d_in[0];      // [B, C_IN, V, 1]
    const int*   Gi   = (const int*)d_in[1];        // [B, V, 4] (int32/int64 probed)
    const float* W    = (const float*)d_in[2];      // [C_OUT, C_IN, 7]
    const float* bias = (const float*)d_in[3];      // [C_OUT]
    float*       out  = (float*)d_out;              // [B, C_OUT, V, 1]

    static bool attr_set = false;
    if (!attr_set) {
        cudaFuncSetAttribute(mesh_main,
                             cudaFuncAttributeMaxDynamicSharedMemorySize,
                             SMEM_TOTAL);
        attr_set = true;
    }

    transpose_kernel<<<dim3((NV + 31) / 32, CIN / 32, BATCH), dim3(32, 8)>>>(x);
    wprep_kernel<<<(NCHUNK * 128 * 120 + 255) / 256, 256>>>(W);
    mesh_main<<<NTILES, NTHREADS, SMEM_TOTAL>>>(Gi, bias, out);
}

// round 14
// speedup vs baseline: 4.3262x; 1.0939x over previous
#include <cuda_runtime.h>
#include <cuda_fp16.h>
#include <cstdint>

// MeshConvPoint via warp-level mma.sync (fp16 HMMA, single-pass), pipelined.
//   out[pts,128] = G[pts,448] @ W[448,128] + bias, fused with gather.
//   fp16 operands, fp32 accumulation: rel_err ~2.9e-4 global-norm.
//
// CTA: 128 points x 128 outputs, 512 threads = 16 warps, warp tile m32n32.
// K = 448 = 4 chunks x 112 (7 k16-steps each), k_local = r*16 + c.
// R14: A AND B double-buffered -> ONE syncthreads per chunk; next chunk's
// cp.async (B copy + gather) issued before the MMA phase so latency hides
// under tensor work; f16x2 packed converts in the feature phase.

#define BATCH    4
#define CIN      64
#define NV       50000
#define COUT     128
#define NK       7
#define CK       (CIN * NK)              // 448
#define NPTS     (BATCH * NV)            // 200000
#define TP       128
#define NTILES   ((NPTS + TP - 1) / TP)  // 1563
#define NTHREADS 512
#define NCHUNK   4
#define KCHUNK   112
#define ROWB     240                     // padded row bytes (120 fp16)
#define TILE_B   (128 * ROWB)            // 30720

// smem layout (bytes)
#define OFF_A    0                        // [2 stage][TILE_B] = 61440
#define OFF_B    (2 * TILE_B)             // [2 stage][TILE_B] = 61440
#define OFF_GRAW (4 * TILE_B)             // 122880: [4][512][16] = 32768
#define OFF_BIAS (OFF_GRAW + 32768)       // 155648: 128 floats
#define SMEM_TOTAL (OFF_BIAS + 512)       // 156160
#define SOUT_PITCH 132                    // epilogue overlay [128][132] f32

// static scratch
__device__ __align__(16) float  g_xT[(size_t)BATCH * NV * CIN];   // 51.2 MB
__device__ __align__(16) __half g_Whf[NCHUNK][128][120];          // fp16 W tiles

__device__ __forceinline__ uint32_t smem_u32(const void* p) {
    uint32_t a;
    asm("{ .reg .u64 t; cvta.to.shared.u64 t, %1; cvt.u32.u64 %0, t; }" : "=r"(a) : "l"(p));
    return a;
}
// pack: d = {hi: half(a), lo: half(b)}
__device__ __forceinline__ uint32_t pack_f16x2(float hi, float lo) {
    uint32_t d;
    asm("cvt.rn.f16x2.f32 %0, %1, %2;" : "=r"(d) : "f"(hi), "f"(lo));
    return d;
}

#define LDMX4(r0, r1, r2, r3, addr) \
    asm volatile("ldmatrix.sync.aligned.m8n8.x4.shared.b16 {%0,%1,%2,%3}, [%4];" \
                 : "=r"(r0), "=r"(r1), "=r"(r2), "=r"(r3) : "r"(addr))

#define MMA16816(d, a0, a1, a2, a3, b0, b1) \
    asm volatile("mma.sync.aligned.m16n8k16.row.col.f32.f16.f16.f32 " \
                 "{%0,%1,%2,%3}, {%4,%5,%6,%7}, {%8,%9}, {%0,%1,%2,%3};" \
                 : "+f"((d)[0]), "+f"((d)[1]), "+f"((d)[2]), "+f"((d)[3]) \
                 : "r"(a0), "r"(a1), "r"(a2), "r"(a3), "r"(b0), "r"(b1))

#define CPA16(dst, src, sz) \
    asm volatile("cp.async.cg.shared.global [%0], [%1], 16, %2;" \
                 :: "r"(dst), "l"(src), "r"(sz))
#define CPCOMMIT() asm volatile("cp.async.commit_group;" ::: "memory")
#define CPWAIT0()  asm volatile("cp.async.wait_group 0;" ::: "memory")

// ---- 1) transpose x [B,C,V] -> xT [B,V,C] ----
__global__ void transpose_kernel(const float* __restrict__ x) {
    __shared__ float tile[32][33];
    int b  = blockIdx.z;
    int cb = blockIdx.y * 32;
    int vb = blockIdx.x * 32;
    int tx = threadIdx.x, ty = threadIdx.y;
#pragma unroll
    for (int i = 0; i < 32; i += 8) {
        int c = cb + ty + i, v = vb + tx;
        if (v < NV) tile[ty + i][tx] = x[((size_t)(b * CIN + c)) * NV + v];
    }
    __syncthreads();
#pragma unroll
    for (int i = 0; i < 32; i += 8) {
        int v = vb + ty + i, c = cb + tx;
        if (v < NV) g_xT[((size_t)(b * NV + v)) * CIN + c] = tile[tx][ty + i];
    }
}

// ---- 2) W -> fp16 tiles [chunk][n=128][k=120], k = r*16 + c ----
__global__ void wprep_kernel(const float* __restrict__ W) {
    int i = blockIdx.x * 256 + threadIdx.x;         // over 4*128*120 = 61440
    if (i >= NCHUNK * 128 * 120) return;
    int kl = i % 120;
    int n  = (i / 120) & 127;
    int ch = i / (120 * 128);
    float v = 0.0f;
    if (kl < KCHUNK) {
        int r = kl >> 4, c = kl & 15;
        v = W[n * CK + (ch * 16 + c) * NK + r];
    }
    g_Whf[ch][n][kl] = __float2half_rn(v);
}

// ---- 3) fused pipelined main kernel ----
__global__ void __launch_bounds__(NTHREADS, 1)
mesh_main(const int* __restrict__ Gi32,
          const float* __restrict__ bias,
          float* __restrict__ out) {
    extern __shared__ char sm[];
    const uint32_t sb = smem_u32(sm);
    const int t    = threadIdx.x;
    const int wid  = t >> 5;
    const int lane = t & 31;
    const int p0   = blockIdx.x * TP;

    float* sBias = (float*)(sm + OFF_BIAS);
    if (t < COUT) sBias[t] = bias[t];

    // per-thread gather task: point gp, 4-channel group gq
    const int gp = t >> 2, gq = t & 3;

    // resolve this thread's 4 neighbor rows (L1-broadcast loads, no smem)
    int rows[4];
    {
        bool is64 = ((Gi32[1] | Gi32[3] | Gi32[5] | Gi32[7]) == 0);
        int pg = p0 + gp;
#pragma unroll
        for (int j = 0; j < 4; j++) {
            int row = -1;
            if (pg < NPTS) {
                int raw = is64 ? Gi32[2 * (pg * 4 + j)] : Gi32[pg * 4 + j];
                if (raw >= 0 && raw < NV) row = (pg / NV) * NV + raw;
            }
            rows[j] = row;
        }
    }

    // warp MMA tiling: 4x4 warps of m32 x n32
    const int mb = (wid & 3) * 32;
    const int nb = (wid >> 2) * 32;
    const int mi = lane >> 3, rowin = lane & 7;
    const uint32_t aOff = (uint32_t)(mb + (mi & 1) * 8 + rowin) * ROWB + (uint32_t)(mi >> 1) * 16;
    const uint32_t bOff = (uint32_t)(nb + (mi >> 1) * 8 + rowin) * ROWB + (uint32_t)(mi & 1) * 16;

    float acc[2][4][4];
#pragma unroll
    for (int a = 0; a < 2; a++)
#pragma unroll
        for (int b = 0; b < 4; b++)
#pragma unroll
            for (int c = 0; c < 4; c++) acc[a][b][c] = 0.0f;

    // cp.async issuers
    auto issue_gather = [&](int ch) {
#pragma unroll
        for (int j = 0; j < 4; j++) {
            const char* src = (const char*)(g_xT +
                ((rows[j] >= 0) ? (size_t)rows[j] * CIN : 0) + (ch * 16 + gq * 4));
            CPA16(sb + OFF_GRAW + (uint32_t)(j * NTHREADS + t) * 16, src,
                  rows[j] >= 0 ? 16u : 0u);
        }
        CPCOMMIT();
    };
    auto issue_bcopy = [&](int ch, int stage) {
        const char* bsrc = (const char*)&g_Whf[ch][0][0];   // 30720B contiguous
        const uint32_t dst = sb + OFF_B + (uint32_t)stage * TILE_B;
        for (int i = t; i < TILE_B / 16; i += NTHREADS)
            CPA16(dst + (uint32_t)i * 16, bsrc + (size_t)i * 16, 16u);
        CPCOMMIT();
    };

    // features: staging -> fp16 A[stage]
    auto features = [&](int stage) {
        float4 v[4];
#pragma unroll
        for (int j = 0; j < 4; j++) {
            uint32_t a = sb + OFF_GRAW + (uint32_t)(j * NTHREADS + t) * 16;
            asm volatile("ld.shared.v4.f32 {%0,%1,%2,%3}, [%4];"
                         : "=f"(v[j].x), "=f"(v[j].y), "=f"(v[j].z), "=f"(v[j].w)
                         : "r"(a));
        }
        const float a0[4] = {v[0].x, v[0].y, v[0].z, v[0].w};
        const float a1[4] = {v[1].x, v[1].y, v[1].z, v[1].w};
        const float a2[4] = {v[2].x, v[2].y, v[2].z, v[2].w};
        const float a3[4] = {v[3].x, v[3].y, v[3].z, v[3].w};
        float sf[NK][4];
#pragma unroll
        for (int ci = 0; ci < 4; ci++) {
            float f0 = a0[ci], f1 = a1[ci], f2 = a2[ci], f3 = a3[ci];
            float p12 = f1 * f2, p13 = f1 * f3, p23 = f2 * f3;
            sf[0][ci] = f0;
            sf[1][ci] = f1 + f2 + f3;
            sf[2][ci] = p12 * f3;
            sf[3][ci] = p12 + p13 + p23;
            sf[4][ci] = f1 * f1 + f2 * f2 + f3 * f3;
            sf[5][ci] = fabsf(f1 - f2) + fabsf(f1 - f3) + fabsf(f2 - f3);
            sf[6][ci] = f1 * f1 * f1 + f2 * f2 * f2 + f3 * f3 * f3;
        }
        char* Ah = sm + OFF_A + stage * TILE_B + gp * ROWB + gq * 8;
#pragma unroll
        for (int r = 0; r < NK; r++) {
            uint32_t w0 = pack_f16x2(sf[r][1], sf[r][0]);   // {hi: ci1, lo: ci0}
            uint32_t w1 = pack_f16x2(sf[r][3], sf[r][2]);   // {hi: ci3, lo: ci2}
            *(uint2*)(Ah + r * 32) = make_uint2(w0, w1);
        }
    };

    // ---- prologue: chunk 0 staged and converted ----
    issue_gather(0);
    issue_bcopy(0, 0);
    CPWAIT0();
    features(0);
    __syncthreads();

    for (int ch = 0; ch < NCHUNK; ch++) {
        const int stage = ch & 1;

        // issue next chunk's async traffic BEFORE the MMA phase (hides there)
        if (ch + 1 < NCHUNK) {
            issue_bcopy(ch + 1, stage ^ 1);   // writes other B buffer
            issue_gather(ch + 1);             // staging free: consumed pre-sync
        }

        // MMA phase: 7 k16-steps, warp tile m32 x n32
        const uint32_t Ab = sb + OFF_A + (uint32_t)stage * TILE_B;
        const uint32_t Bb = sb + OFF_B + (uint32_t)stage * TILE_B;
#pragma unroll
        for (int ks = 0; ks < 7; ks++) {
            const uint32_t kb = (uint32_t)ks * 32;
            uint32_t a0, a1, a2, a3, a4, a5, a6, a7;
            LDMX4(a0, a1, a2, a3, Ab + aOff + kb);
            LDMX4(a4, a5, a6, a7, Ab + aOff + 16 * ROWB + kb);
            uint32_t b0, b1, b2, b3, b4, b5, b6, b7;
            LDMX4(b0, b1, b2, b3, Bb + bOff + kb);
            LDMX4(b4, b5, b6, b7, Bb + bOff + 16 * ROWB + kb);

            MMA16816(acc[0][0], a0, a1, a2, a3, b0, b1);
            MMA16816(acc[0][1], a0, a1, a2, a3, b2, b3);
            MMA16816(acc[0][2], a0, a1, a2, a3, b4, b5);
            MMA16816(acc[0][3], a0, a1, a2, a3, b6, b7);
            MMA16816(acc[1][0], a4, a5, a6, a7, b0, b1);
            MMA16816(acc[1][1], a4, a5, a6, a7, b2, b3);
            MMA16816(acc[1][2], a4, a5, a6, a7, b4, b5);
            MMA16816(acc[1][3], a4, a5, a6, a7, b6, b7);
        }

        if (ch + 1 < NCHUNK) {
            CPWAIT0();                 // gather(ch+1) + B(ch+1) landed
            features(stage ^ 1);       // fill other A buffer (no reader conflict)
        }
        __syncthreads();               // publish A/B[stage^1]; MMA(ch) done CTA-wide
    }

    // ---- epilogue: d-frags -> sOut[p][o], then coalesced global stores ----
    float* sOut = (float*)sm;          // [128][SOUT_PITCH] overlay on A/B tiles
    {
        const int r4 = lane >> 2, c2 = 2 * (lane & 3);
#pragma unroll
        for (int mt = 0; mt < 2; mt++) {
            const int prow = mb + mt * 16 + r4;
#pragma unroll
            for (int ng = 0; ng < 4; ng++) {
                const int n = nb + ng * 8 + c2;
                *(float2*)&sOut[prow * SOUT_PITCH + n] =
                    make_float2(acc[mt][ng][0], acc[mt][ng][1]);
                *(float2*)&sOut[(prow + 8) * SOUT_PITCH + n] =
                    make_float2(acc[mt][ng][2], acc[mt][ng][3]);
            }
        }
    }
    __syncthreads();

    for (int idx = t; idx < COUT * TP; idx += NTHREADS) {
        int o  = idx >> 7;
        int vl = idx & 127;
        int pg = p0 + vl;
        if (pg < NPTS) {
            int b = pg / NV;
            int v = pg - b * NV;
            out[((size_t)(b * COUT + o)) * NV + v] = sOut[vl * SOUT_PITCH + o] + sBias[o];
        }
    }
}

extern "C" void kernel_launch(void* const* d_in, const int* in_sizes, int n_in,
                              void* d_out, int out_size) {
    const float* x    = (const float*)d_in[0];      // [B, C_IN, V, 1]
    const int*   Gi   = (const int*)d_in[1];        // [B, V, 4] (int32/int64 probed)
    const float* W    = (const float*)d_in[2];      // [C_OUT, C_IN, 7]
    const float* bias = (const float*)d_in[3];      // [C_OUT]
    float*       out  = (float*)d_out;              // [B, C_OUT, V, 1]

    static bool attr_set = false;
    if (!attr_set) {
        cudaFuncSetAttribute(mesh_main,
                             cudaFuncAttributeMaxDynamicSharedMemorySize,
                             SMEM_TOTAL);
        attr_set = true;
    }

    transpose_kernel<<<dim3((NV + 31) / 32, CIN / 32, BATCH), dim3(32, 8)>>>(x);
    wprep_kernel<<<(NCHUNK * 128 * 120 + 255) / 256, 256>>>(W);
    mesh_main<<<NTILES, NTHREADS, SMEM_TOTAL>>>(Gi, bias, out);
}

// round 15
// speedup vs baseline: 4.7904x; 1.1073x over previous
#include <cuda_runtime.h>
#include <cuda_fp16.h>
#include <cstdint>

// MeshConvPoint via warp-level mma.sync (fp16 HMMA, single-pass), pipelined.
//   out[pts,128] = G[pts,448] @ W[448,128] + bias, fused with gather.
//   fp16 operands, fp32 accumulation: rel_err ~2.9e-4 global-norm.
//
// R15: occupancy 2. CTA = 64 points x 128 outputs, 256 threads = 8 warps
// (warp tile m32n32). smem 109 KB -> 2 CTAs/SM; the sibling CTA's MMA stream
// fills this CTA's feature/barrier/prologue bubbles.
// K = 448 = 4 chunks x 112 (7 k16-steps), k_local = r*16 + c.
// A and B double-buffered; one syncthreads per chunk; next chunk's cp.async
// (B copy + gather) issued before the MMA phase.

#define BATCH    4
#define CIN      64
#define NV       50000
#define COUT     128
#define NK       7
#define CK       (CIN * NK)              // 448
#define NPTS     (BATCH * NV)            // 200000
#define TP       64
#define NTILES   ((NPTS + TP - 1) / TP)  // 3125
#define NTHREADS 256
#define NCHUNK   4
#define KCHUNK   112
#define ROWB     240                     // padded row bytes (120 fp16)
#define TILE_A   (TP * ROWB)             // 15360 (A tile: 64 rows)
#define TILE_B   (128 * ROWB)            // 30720 (B tile: 128 rows)

// smem layout (bytes)
#define OFF_A    0                        // [2 stage][TILE_A] = 30720
#define OFF_B    (2 * TILE_A)             // [2 stage][TILE_B] = 61440
#define OFF_GRAW (OFF_B + 2 * TILE_B)     // 92160: [4][256][16] = 16384
#define OFF_BIAS (OFF_GRAW + 16384)       // 108544: 128 floats
#define SMEM_TOTAL (OFF_BIAS + 512)       // 109056
#define SOUT_PITCH 132                    // epilogue overlay [64][132] f32

// static scratch
__device__ __align__(16) float  g_xT[(size_t)BATCH * NV * CIN];   // 51.2 MB
__device__ __align__(16) __half g_Whf[NCHUNK][128][120];          // fp16 W tiles

__device__ __forceinline__ uint32_t smem_u32(const void* p) {
    uint32_t a;
    asm("{ .reg .u64 t; cvta.to.shared.u64 t, %1; cvt.u32.u64 %0, t; }" : "=r"(a) : "l"(p));
    return a;
}
// pack: d = {hi: half(a), lo: half(b)}
__device__ __forceinline__ uint32_t pack_f16x2(float hi, float lo) {
    uint32_t d;
    asm("cvt.rn.f16x2.f32 %0, %1, %2;" : "=r"(d) : "f"(hi), "f"(lo));
    return d;
}

#define LDMX4(r0, r1, r2, r3, addr) \
    asm volatile("ldmatrix.sync.aligned.m8n8.x4.shared.b16 {%0,%1,%2,%3}, [%4];" \
                 : "=r"(r0), "=r"(r1), "=r"(r2), "=r"(r3) : "r"(addr))

#define MMA16816(d, a0, a1, a2, a3, b0, b1) \
    asm volatile("mma.sync.aligned.m16n8k16.row.col.f32.f16.f16.f32 " \
                 "{%0,%1,%2,%3}, {%4,%5,%6,%7}, {%8,%9}, {%0,%1,%2,%3};" \
                 : "+f"((d)[0]), "+f"((d)[1]), "+f"((d)[2]), "+f"((d)[3]) \
                 : "r"(a0), "r"(a1), "r"(a2), "r"(a3), "r"(b0), "r"(b1))

#define CPA16(dst, src, sz) \
    asm volatile("cp.async.cg.shared.global [%0], [%1], 16, %2;" \
                 :: "r"(dst), "l"(src), "r"(sz))
#define CPCOMMIT() asm volatile("cp.async.commit_group;" ::: "memory")
#define CPWAIT0()  asm volatile("cp.async.wait_group 0;" ::: "memory")

// ---- 1) transpose x [B,C,V] -> xT [B,V,C] ----
__global__ void transpose_kernel(const float* __restrict__ x) {
    __shared__ float tile[32][33];
    int b  = blockIdx.z;
    int cb = blockIdx.y * 32;
    int vb = blockIdx.x * 32;
    int tx = threadIdx.x, ty = threadIdx.y;
#pragma unroll
    for (int i = 0; i < 32; i += 8) {
        int c = cb + ty + i, v = vb + tx;
        if (v < NV) tile[ty + i][tx] = x[((size_t)(b * CIN + c)) * NV + v];
    }
    __syncthreads();
#pragma unroll
    for (int i = 0; i < 32; i += 8) {
        int v = vb + ty + i, c = cb + tx;
        if (v < NV) g_xT[((size_t)(b * NV + v)) * CIN + c] = tile[tx][ty + i];
    }
}

// ---- 2) W -> fp16 tiles [chunk][n=128][k=120], k = r*16 + c ----
__global__ void wprep_kernel(const float* __restrict__ W) {
    int i = blockIdx.x * 256 + threadIdx.x;         // over 4*128*120 = 61440
    if (i >= NCHUNK * 128 * 120) return;
    int kl = i % 120;
    int n  = (i / 120) & 127;
    int ch = i / (120 * 128);
    float v = 0.0f;
    if (kl < KCHUNK) {
        int r = kl >> 4, c = kl & 15;
        v = W[n * CK + (ch * 16 + c) * NK + r];
    }
    g_Whf[ch][n][kl] = __float2half_rn(v);
}

// ---- 3) fused pipelined main kernel (occupancy 2) ----
__global__ void __launch_bounds__(NTHREADS, 2)
mesh_main(const int* __restrict__ Gi32,
          const float* __restrict__ bias,
          float* __restrict__ out) {
    extern __shared__ char sm[];
    const uint32_t sb = smem_u32(sm);
    const int t    = threadIdx.x;
    const int wid  = t >> 5;
    const int lane = t & 31;
    const int p0   = blockIdx.x * TP;

    float* sBias = (float*)(sm + OFF_BIAS);
    if (t < COUT) sBias[t] = bias[t];

    // per-thread gather task: point gp (0..63), 4-channel group gq (0..3)
    const int gp = t >> 2, gq = t & 3;

    // resolve this thread's 4 neighbor rows (L1-broadcast loads, no smem)
    int rows[4];
    {
        bool is64 = ((Gi32[1] | Gi32[3] | Gi32[5] | Gi32[7]) == 0);
        int pg = p0 + gp;
#pragma unroll
        for (int j = 0; j < 4; j++) {
            int row = -1;
            if (pg < NPTS) {
                int raw = is64 ? Gi32[2 * (pg * 4 + j)] : Gi32[pg * 4 + j];
                if (raw >= 0 && raw < NV) row = (pg / NV) * NV + raw;
            }
            rows[j] = row;
        }
    }

    // warp MMA tiling: 2x4 warps of m32 x n32 (8 warps)
    const int mb = (wid & 1) * 32;
    const int nb = (wid >> 1) * 32;
    const int mi = lane >> 3, rowin = lane & 7;
    const uint32_t aOff = (uint32_t)(mb + (mi & 1) * 8 + rowin) * ROWB + (uint32_t)(mi >> 1) * 16;
    const uint32_t bOff = (uint32_t)(nb + (mi >> 1) * 8 + rowin) * ROWB + (uint32_t)(mi & 1) * 16;

    float acc[2][4][4];
#pragma unroll
    for (int a = 0; a < 2; a++)
#pragma unroll
        for (int b = 0; b < 4; b++)
#pragma unroll
            for (int c = 0; c < 4; c++) acc[a][b][c] = 0.0f;

    // cp.async issuers
    auto issue_gather = [&](int ch) {
#pragma unroll
        for (int j = 0; j < 4; j++) {
            const char* src = (const char*)(g_xT +
                ((rows[j] >= 0) ? (size_t)rows[j] * CIN : 0) + (ch * 16 + gq * 4));
            CPA16(sb + OFF_GRAW + (uint32_t)(j * NTHREADS + t) * 16, src,
                  rows[j] >= 0 ? 16u : 0u);
        }
        CPCOMMIT();
    };
    auto issue_bcopy = [&](int ch, int stage) {
        const char* bsrc = (const char*)&g_Whf[ch][0][0];   // 30720B contiguous
        const uint32_t dst = sb + OFF_B + (uint32_t)stage * TILE_B;
        for (int i = t; i < TILE_B / 16; i += NTHREADS)
            CPA16(dst + (uint32_t)i * 16, bsrc + (size_t)i * 16, 16u);
        CPCOMMIT();
    };

    // features: staging -> fp16 A[stage]
    auto features = [&](int stage) {
        float4 v[4];
#pragma unroll
        for (int j = 0; j < 4; j++) {
            uint32_t a = sb + OFF_GRAW + (uint32_t)(j * NTHREADS + t) * 16;
            asm volatile("ld.shared.v4.f32 {%0,%1,%2,%3}, [%4];"
                         : "=f"(v[j].x), "=f"(v[j].y), "=f"(v[j].z), "=f"(v[j].w)
                         : "r"(a));
        }
        const float a0[4] = {v[0].x, v[0].y, v[0].z, v[0].w};
        const float a1[4] = {v[1].x, v[1].y, v[1].z, v[1].w};
        const float a2[4] = {v[2].x, v[2].y, v[2].z, v[2].w};
        const float a3[4] = {v[3].x, v[3].y, v[3].z, v[3].w};
        float sf[NK][4];
#pragma unroll
        for (int ci = 0; ci < 4; ci++) {
            float f0 = a0[ci], f1 = a1[ci], f2 = a2[ci], f3 = a3[ci];
            float p12 = f1 * f2, p13 = f1 * f3, p23 = f2 * f3;
            sf[0][ci] = f0;
            sf[1][ci] = f1 + f2 + f3;
            sf[2][ci] = p12 * f3;
            sf[3][ci] = p12 + p13 + p23;
            sf[4][ci] = f1 * f1 + f2 * f2 + f3 * f3;
            sf[5][ci] = fabsf(f1 - f2) + fabsf(f1 - f3) + fabsf(f2 - f3);
            sf[6][ci] = f1 * f1 * f1 + f2 * f2 * f2 + f3 * f3 * f3;
        }
        char* Ah = sm + OFF_A + stage * TILE_A + gp * ROWB + gq * 8;
#pragma unroll
        for (int r = 0; r < NK; r++) {
            uint32_t w0 = pack_f16x2(sf[r][1], sf[r][0]);   // {hi: ci1, lo: ci0}
            uint32_t w1 = pack_f16x2(sf[r][3], sf[r][2]);   // {hi: ci3, lo: ci2}
            *(uint2*)(Ah + r * 32) = make_uint2(w0, w1);
        }
    };

    // ---- prologue: chunk 0 staged and converted ----
    issue_gather(0);
    issue_bcopy(0, 0);
    CPWAIT0();
    features(0);
    __syncthreads();

    for (int ch = 0; ch < NCHUNK; ch++) {
        const int stage = ch & 1;

        // issue next chunk's async traffic BEFORE the MMA phase (hides there)
        if (ch + 1 < NCHUNK) {
            issue_bcopy(ch + 1, stage ^ 1);   // writes other B buffer
            issue_gather(ch + 1);             // staging free: consumed pre-sync
        }

        // MMA phase: 7 k16-steps, warp tile m32 x n32
        const uint32_t Ab = sb + OFF_A + (uint32_t)stage * TILE_A;
        const uint32_t Bb = sb + OFF_B + (uint32_t)stage * TILE_B;
#pragma unroll
        for (int ks = 0; ks < 7; ks++) {
            const uint32_t kb = (uint32_t)ks * 32;
            uint32_t a0, a1, a2, a3, a4, a5, a6, a7;
            LDMX4(a0, a1, a2, a3, Ab + aOff + kb);
            LDMX4(a4, a5, a6, a7, Ab + aOff + 16 * ROWB + kb);
            uint32_t b0, b1, b2, b3, b4, b5, b6, b7;
            LDMX4(b0, b1, b2, b3, Bb + bOff + kb);
            LDMX4(b4, b5, b6, b7, Bb + bOff + 16 * ROWB + kb);

            MMA16816(acc[0][0], a0, a1, a2, a3, b0, b1);
            MMA16816(acc[0][1], a0, a1, a2, a3, b2, b3);
            MMA16816(acc[0][2], a0, a1, a2, a3, b4, b5);
            MMA16816(acc[0][3], a0, a1, a2, a3, b6, b7);
            MMA16816(acc[1][0], a4, a5, a6, a7, b0, b1);
            MMA16816(acc[1][1], a4, a5, a6, a7, b2, b3);
            MMA16816(acc[1][2], a4, a5, a6, a7, b4, b5);
            MMA16816(acc[1][3], a4, a5, a6, a7, b6, b7);
        }

        if (ch + 1 < NCHUNK) {
            CPWAIT0();                 // gather(ch+1) + B(ch+1) landed
            features(stage ^ 1);       // fill other A buffer (no reader conflict)
        }
        __syncthreads();               // publish A/B[stage^1]; MMA(ch) done CTA-wide
    }

    // ---- epilogue: d-frags -> sOut[p][o], then coalesced global stores ----
    float* sOut = (float*)sm;          // [64][SOUT_PITCH] overlay on A/B tiles
    {
        const int r4 = lane >> 2, c2 = 2 * (lane & 3);
#pragma unroll
        for (int mt = 0; mt < 2; mt++) {
            const int prow = mb + mt * 16 + r4;
#pragma unroll
            for (int ng = 0; ng < 4; ng++) {
                const int n = nb + ng * 8 + c2;
                *(float2*)&sOut[prow * SOUT_PITCH + n] =
                    make_float2(acc[mt][ng][0], acc[mt][ng][1]);
                *(float2*)&sOut[(prow + 8) * SOUT_PITCH + n] =
                    make_float2(acc[mt][ng][2], acc[mt][ng][3]);
            }
        }
    }
    __syncthreads();

    for (int idx = t; idx < COUT * TP; idx += NTHREADS) {
        int o  = idx >> 6;             // 0..127
        int vl = idx & 63;             // 0..63
        int pg = p0 + vl;
        if (pg < NPTS) {
            int b = pg / NV;
            int v = pg - b * NV;
            out[((size_t)(b * COUT + o)) * NV + v] = sOut[vl * SOUT_PITCH + o] + sBias[o];
        }
    }
}

extern "C" void kernel_launch(void* const* d_in, const int* in_sizes, int n_in,
                              void* d_out, int out_size) {
    const float* x    = (const float*)d_in[0];      // [B, C_IN, V, 1]
    const int*   Gi   = (const int*)d_in[1];        // [B, V, 4] (int32/int64 probed)
    const float* W    = (const float*)d_in[2];      // [C_OUT, C_IN, 7]
    const float* bias = (const float*)d_in[3];      // [C_OUT]
    float*       out  = (float*)d_out;              // [B, C_OUT, V, 1]

    static bool attr_set = false;
    if (!attr_set) {
        cudaFuncSetAttribute(mesh_main,
                             cudaFuncAttributeMaxDynamicSharedMemorySize,
                             SMEM_TOTAL);
        attr_set = true;
    }

    transpose_kernel<<<dim3((NV + 31) / 32, CIN / 32, BATCH), dim3(32, 8)>>>(x);
    wprep_kernel<<<(NCHUNK * 128 * 120 + 255) / 256, 256>>>(W);
    mesh_main<<<NTILES, NTHREADS, SMEM_TOTAL>>>(Gi, bias, out);
}